// round 1
// baseline (speedup 1.0000x reference)
#include <cuda_runtime.h>
#include <cuda_bf16.h>
#include <math.h>

// Problem dims (fixed by the reference)
#define BB 16
#define CC 256
#define LL 2048
#define EPS 1e-5f

// ---------------------------------------------------------------------------
// Scratch (no cudaMalloc allowed -> __device__ globals)
// ---------------------------------------------------------------------------
__device__ float d_g    [(size_t)BB * CC * LL];          // 33.5 MB
__device__ float d_theta[(size_t)BB * CC * LL];
__device__ float d_phi  [(size_t)BB * CC * LL];
__device__ float d_f    [(size_t)BB * LL * LL];          // 268 MB (softmax in-place)
__device__ float d_y    [(size_t)BB * CC * LL];
__device__ float d_wy   [(size_t)BB * CC * LL];
__device__ float d_mean [CC];
__device__ float d_rstd [CC];

// ---------------------------------------------------------------------------
// Generic batched SGEMM: C[m,n] = sum_k A(m,k)*B(k,n) (+ bias[m])
//   TA==0: A(m,k)=A[m*lda+k]   TA==1: A(m,k)=A[k*lda+m]
//   TB==0: B(k,n)=B[k*ldb+n]   TB==1: B(k,n)=B[n*ldb+k]
// Tiles: 128x128x16, 256 threads, 8x8 per-thread micro-tile with split-64
// column/row layout for conflict-free float4 smem reads.
// ---------------------------------------------------------------------------
template<int TA, int TB>
__global__ __launch_bounds__(256, 2)
void sgemm_kernel(const float* __restrict__ A, const float* __restrict__ B,
                  const float* __restrict__ bias, float* __restrict__ Cout,
                  int M, int N, int K, int lda, int ldb, int ldc,
                  size_t sA, size_t sB, size_t sC)
{
    constexpr int BM = 128, BN = 128, BK = 16;
    __shared__ float As[BK][BM];
    __shared__ float Bs[BK][BN];

    A    += (size_t)blockIdx.z * sA;
    B    += (size_t)blockIdx.z * sB;
    Cout += (size_t)blockIdx.z * sC;

    const int tid  = threadIdx.x;
    const int tcol = tid & 15;   // 16 cols of threads
    const int trow = tid >> 4;   // 16 rows of threads
    const int mBase = blockIdx.y * BM;
    const int nBase = blockIdx.x * BN;

    float acc[8][8];
#pragma unroll
    for (int i = 0; i < 8; i++)
#pragma unroll
        for (int j = 0; j < 8; j++) acc[i][j] = 0.f;

    for (int k0 = 0; k0 < K; k0 += BK) {
        // ---- load A tile into As[k][m] ----
        if (TA == 0) {
#pragma unroll
            for (int t = tid; t < BM * BK; t += 256) {
                int k = t & (BK - 1), m = t >> 4;
                As[k][m] = A[(size_t)(mBase + m) * lda + (k0 + k)];
            }
        } else {
#pragma unroll
            for (int t = tid; t < BM * BK; t += 256) {
                int m = t & (BM - 1), k = t >> 7;
                As[k][m] = A[(size_t)(k0 + k) * lda + (mBase + m)];
            }
        }
        // ---- load B tile into Bs[k][n] ----
        if (TB == 0) {
#pragma unroll
            for (int t = tid; t < BK * BN; t += 256) {
                int n = t & (BN - 1), k = t >> 7;
                Bs[k][n] = B[(size_t)(k0 + k) * ldb + (nBase + n)];
            }
        } else {
#pragma unroll
            for (int t = tid; t < BK * BN; t += 256) {
                int k = t & (BK - 1), n = t >> 4;
                Bs[k][n] = B[(size_t)(nBase + n) * ldb + (k0 + k)];
            }
        }
        __syncthreads();

#pragma unroll
        for (int k = 0; k < BK; k++) {
            float a[8], b[8];
            *(float4*)&a[0] = *(const float4*)&As[k][trow * 4];
            *(float4*)&a[4] = *(const float4*)&As[k][64 + trow * 4];
            *(float4*)&b[0] = *(const float4*)&Bs[k][tcol * 4];
            *(float4*)&b[4] = *(const float4*)&Bs[k][64 + tcol * 4];
#pragma unroll
            for (int i = 0; i < 8; i++)
#pragma unroll
                for (int j = 0; j < 8; j++)
                    acc[i][j] += a[i] * b[j];
        }
        __syncthreads();
    }

    // ---- epilogue: optional bias, float4 stores ----
#pragma unroll
    for (int i = 0; i < 8; i++) {
        int m = mBase + ((i < 4) ? (trow * 4 + i) : (64 + trow * 4 + i - 4));
        float bv = bias ? bias[m] : 0.f;
        float4 v0, v1;
        v0.x = acc[i][0] + bv; v0.y = acc[i][1] + bv;
        v0.z = acc[i][2] + bv; v0.w = acc[i][3] + bv;
        v1.x = acc[i][4] + bv; v1.y = acc[i][5] + bv;
        v1.z = acc[i][6] + bv; v1.w = acc[i][7] + bv;
        *(float4*)&Cout[(size_t)m * ldc + nBase + tcol * 4]      = v0;
        *(float4*)&Cout[(size_t)m * ldc + nBase + 64 + tcol * 4] = v1;
    }
}

// ---------------------------------------------------------------------------
// Row softmax over rows of length LL (in-place). One block (256 thr) per row.
// ---------------------------------------------------------------------------
__global__ __launch_bounds__(256)
void softmax_kernel(float* __restrict__ f)
{
    __shared__ float red[8];
    float* p = f + (size_t)blockIdx.x * LL;
    const int tid = threadIdx.x;

    float v[8];
    float m = -INFINITY;
#pragma unroll
    for (int j = 0; j < 8; j++) {
        v[j] = p[tid + j * 256];
        m = fmaxf(m, v[j]);
    }
#pragma unroll
    for (int o = 16; o; o >>= 1) m = fmaxf(m, __shfl_xor_sync(0xffffffffu, m, o));
    if ((tid & 31) == 0) red[tid >> 5] = m;
    __syncthreads();
    float bm = red[0];
#pragma unroll
    for (int w = 1; w < 8; w++) bm = fmaxf(bm, red[w]);

    float s = 0.f;
#pragma unroll
    for (int j = 0; j < 8; j++) {
        v[j] = expf(v[j] - bm);
        s += v[j];
    }
#pragma unroll
    for (int o = 16; o; o >>= 1) s += __shfl_xor_sync(0xffffffffu, s, o);
    __syncthreads();
    if ((tid & 31) == 0) red[tid >> 5] = s;
    __syncthreads();
    float bs = 0.f;
#pragma unroll
    for (int w = 0; w < 8; w++) bs += red[w];
    float inv = 1.f / bs;
#pragma unroll
    for (int j = 0; j < 8; j++) p[tid + j * 256] = v[j] * inv;
}

// ---------------------------------------------------------------------------
// BatchNorm batch stats: one block per channel, reduce over (B, L)
// ---------------------------------------------------------------------------
__global__ __launch_bounds__(256)
void bn_stats_kernel(const float* __restrict__ wy,
                     float* __restrict__ mean, float* __restrict__ rstd)
{
    __shared__ float rs[8], rss[8];
    const int c = blockIdx.x;
    float s = 0.f, ss = 0.f;
    for (int t = threadIdx.x; t < BB * LL; t += 256) {
        int b = t >> 11;          // t / LL
        int l = t & (LL - 1);
        float v = wy[(size_t)b * CC * LL + (size_t)c * LL + l];
        s += v; ss += v * v;
    }
#pragma unroll
    for (int o = 16; o; o >>= 1) {
        s  += __shfl_xor_sync(0xffffffffu, s,  o);
        ss += __shfl_xor_sync(0xffffffffu, ss, o);
    }
    if ((threadIdx.x & 31) == 0) { rs[threadIdx.x >> 5] = s; rss[threadIdx.x >> 5] = ss; }
    __syncthreads();
    if (threadIdx.x == 0) {
        float ts = 0.f, tss = 0.f;
#pragma unroll
        for (int w = 0; w < 8; w++) { ts += rs[w]; tss += rss[w]; }
        float inv_n = 1.f / (float)(BB * LL);
        float mu  = ts * inv_n;
        float var = tss * inv_n - mu * mu;
        mean[c] = mu;
        rstd[c] = rsqrtf(var + EPS);
    }
}

// ---------------------------------------------------------------------------
// Final: gamma*(wy-mu)*rstd + beta + x
// ---------------------------------------------------------------------------
__global__ __launch_bounds__(256)
void bn_apply_kernel(const float* __restrict__ wy, const float* __restrict__ x,
                     const float* __restrict__ gamma, const float* __restrict__ beta,
                     const float* __restrict__ mean, const float* __restrict__ rstd,
                     float* __restrict__ out)
{
    size_t i = (size_t)blockIdx.x * 256 + threadIdx.x;
    int c = (int)((i >> 11) & (CC - 1));   // (i / LL) % CC
    out[i] = gamma[c] * (wy[i] - mean[c]) * rstd[c] + beta[c] + x[i];
}

// ---------------------------------------------------------------------------
// Launch
// ---------------------------------------------------------------------------
extern "C" void kernel_launch(void* const* d_in, const int* in_sizes, int n_in,
                              void* d_out, int out_size)
{
    const float* x     = (const float*)d_in[0];
    const float* Wg    = (const float*)d_in[1];
    const float* bg    = (const float*)d_in[2];
    const float* Wt    = (const float*)d_in[3];
    const float* bt    = (const float*)d_in[4];
    const float* Wp    = (const float*)d_in[5];
    const float* bp    = (const float*)d_in[6];
    const float* Ww    = (const float*)d_in[7];
    const float* bw    = (const float*)d_in[8];
    const float* gamma = (const float*)d_in[9];
    const float* beta  = (const float*)d_in[10];
    float* out = (float*)d_out;

    float *g, *theta, *phi, *f, *y, *wy, *mean, *rstd;
    cudaGetSymbolAddress((void**)&g,     d_g);
    cudaGetSymbolAddress((void**)&theta, d_theta);
    cudaGetSymbolAddress((void**)&phi,   d_phi);
    cudaGetSymbolAddress((void**)&f,     d_f);
    cudaGetSymbolAddress((void**)&y,     d_y);
    cudaGetSymbolAddress((void**)&wy,    d_wy);
    cudaGetSymbolAddress((void**)&mean,  d_mean);
    cudaGetSymbolAddress((void**)&rstd,  d_rstd);

    const size_t sX = (size_t)CC * LL;   // per-batch stride for (C,L) tensors
    const size_t sF = (size_t)LL * LL;   // per-batch stride for (L,L)

    // --- Stage 1: pointwise convs g, theta, phi (M=C, N=L, K=C per batch) ---
    {
        dim3 grid(LL / 128, CC / 128, BB);
        sgemm_kernel<0, 0><<<grid, 256>>>(Wg, x, bg, g,     CC, LL, CC, CC, LL, LL, 0, sX, sX);
        sgemm_kernel<0, 0><<<grid, 256>>>(Wt, x, bt, theta, CC, LL, CC, CC, LL, LL, 0, sX, sX);
        sgemm_kernel<0, 0><<<grid, 256>>>(Wp, x, bp, phi,   CC, LL, CC, CC, LL, LL, 0, sX, sX);
    }

    // --- Stage 2: f[l,m] = sum_c theta[c,l] * phi[c,m]  (M=N=L, K=C) ---
    {
        dim3 grid(LL / 128, LL / 128, BB);
        sgemm_kernel<1, 0><<<grid, 256>>>(theta, phi, nullptr, f, LL, LL, CC, LL, LL, LL, sX, sX, sF);
    }

    // --- Stage 3: softmax over last dim of f, in place ---
    softmax_kernel<<<BB * LL, 256>>>(f);

    // --- Stage 4: y[c,l] = sum_m g[c,m] * P[l,m]  (M=C, N=L, K=L) ---
    {
        dim3 grid(LL / 128, CC / 128, BB);
        sgemm_kernel<0, 1><<<grid, 256>>>(g, f, nullptr, y, CC, LL, LL, LL, LL, LL, sX, sF, sX);
    }

    // --- Stage 5: W_y = Ww . y + bw ---
    {
        dim3 grid(LL / 128, CC / 128, BB);
        sgemm_kernel<0, 0><<<grid, 256>>>(Ww, y, bw, wy, CC, LL, CC, CC, LL, LL, 0, sX, sX);
    }

    // --- Stage 6: BN batch stats ---
    bn_stats_kernel<<<CC, 256>>>(wy, mean, rstd);

    // --- Stage 7: normalize + residual ---
    bn_apply_kernel<<<(BB * CC * LL) / 256, 256>>>(wy, x, gamma, beta, mean, rstd, out);
}